// round 6
// baseline (speedup 1.0000x reference)
#include <cuda_runtime.h>
#include <cstdint>

#define SEQ   4096
#define DM    1024
#define HD    128
#define BATCH 4
#define NQT   32          // SEQ / 128
#define SCALE 0.08838834764831845f

__device__ float g_Q[BATCH*SEQ*HD];
__device__ float g_K[BATCH*SEQ*HD];
__device__ float g_V[BATCH*SEQ*HD];
__device__ float g_Op4[4][BATCH*SEQ*HD];
__device__ float g_lp4[4][BATCH*SEQ];

// ---------------- helpers ----------------
__device__ __forceinline__ uint32_t tf32r(float x) {
    uint32_t u;
    asm("cvt.rna.tf32.f32 %0, %1;" : "=r"(u) : "f"(x));
    return u;
}
__device__ __forceinline__ float tf32f(float x) { return __uint_as_float(tf32r(x)); }

__device__ __forceinline__ void mma8(float4& d, const uint32_t a[4], const uint32_t b[2]) {
    asm volatile(
        "mma.sync.aligned.m16n8k8.row.col.f32.tf32.tf32.f32 "
        "{%0,%1,%2,%3}, {%4,%5,%6,%7}, {%8,%9}, {%0,%1,%2,%3};"
        : "+f"(d.x), "+f"(d.y), "+f"(d.z), "+f"(d.w)
        : "r"(a[0]), "r"(a[1]), "r"(a[2]), "r"(a[3]), "r"(b[0]), "r"(b[1]));
}

// ---------------------------------------------------------------------------
// QKV projection: C[16384,128] = x[16384,1024] @ W[1024,128]
// 512 threads, 16 warps (8m x 2n), warp tile 16x64, K chunk 32,
// x split hi/lo tf32 (two A passes), W single tf32.
// ---------------------------------------------------------------------------
#define PA 36     // A smem row stride (floats)
#define PB 132    // B smem row stride
#define PROJ_SMEM ((2*128*PA + 32*PB) * 4)   // 53760 B

__global__ __launch_bounds__(512, 1)
void qkv_mma(const float* __restrict__ x,
             const float* __restrict__ Wq,
             const float* __restrict__ Wk,
             const float* __restrict__ Wv)
{
    extern __shared__ float sm[];
    float* Ah = sm;                 // [128][36]
    float* Al = Ah + 128 * PA;      // [128][36]
    float* Bs = Al + 128 * PA;      // [32][132]

    const int tid  = threadIdx.x;
    const int lane = tid & 31, wid = tid >> 5;
    const int gr = lane >> 2, gc = lane & 3;
    const int wm = wid & 7, wn = wid >> 3;   // warp tile: rows wm*16..+15, cols wn*64..+63

    const int wsel = blockIdx.y;
    const float* __restrict__ W = (wsel == 0) ? Wq : (wsel == 1) ? Wk : Wv;
    float* __restrict__ C = (wsel == 0) ? g_Q : (wsel == 1) ? g_K : g_V;
    const int m0 = blockIdx.x * 128;

    float4 acc[8];
    #pragma unroll
    for (int j = 0; j < 8; j++) acc[j] = make_float4(0.f, 0.f, 0.f, 0.f);

    float4 ra[2], rb[2];
    // prefetch chunk 0
    #pragma unroll
    for (int t = 0; t < 2; ++t) {
        int i = tid + t * 512;
        int r = i >> 3, c4 = i & 7;
        ra[t] = *(const float4*)&x[(size_t)(m0 + r) * DM + c4 * 4];
        int rr = i >> 5, cc = i & 31;
        rb[t] = *(const float4*)&W[(size_t)rr * HD + cc * 4];
    }

    for (int kc = 0; kc < 32; ++kc) {
        // regs -> smem (tf32 split for A)
        #pragma unroll
        for (int t = 0; t < 2; ++t) {
            int i = tid + t * 512;
            int r = i >> 3, c4 = i & 7;
            float4 v = ra[t], h, l;
            h.x = tf32f(v.x); l.x = tf32f(v.x - h.x);
            h.y = tf32f(v.y); l.y = tf32f(v.y - h.y);
            h.z = tf32f(v.z); l.z = tf32f(v.z - h.z);
            h.w = tf32f(v.w); l.w = tf32f(v.w - h.w);
            *(float4*)&Ah[r * PA + c4 * 4] = h;
            *(float4*)&Al[r * PA + c4 * 4] = l;
            int rr = i >> 5, cc = i & 31;
            float4 w4 = rb[t];
            w4.x = tf32f(w4.x); w4.y = tf32f(w4.y); w4.z = tf32f(w4.z); w4.w = tf32f(w4.w);
            *(float4*)&Bs[rr * PB + cc * 4] = w4;
        }
        __syncthreads();
        if (kc < 31) {   // prefetch next chunk
            #pragma unroll
            for (int t = 0; t < 2; ++t) {
                int i = tid + t * 512;
                int r = i >> 3, c4 = i & 7;
                ra[t] = *(const float4*)&x[(size_t)(m0 + r) * DM + (kc + 1) * 32 + c4 * 4];
                int rr = i >> 5, cc = i & 31;
                rb[t] = *(const float4*)&W[(size_t)((kc + 1) * 32 + rr) * HD + cc * 4];
            }
        }
        #pragma unroll
        for (int ks = 0; ks < 4; ++ks) {
            const int k0 = ks * 8;
            uint32_t bf[8][2];
            #pragma unroll
            for (int nf = 0; nf < 8; ++nf) {
                int n = wn * 64 + nf * 8 + gr;
                bf[nf][0] = __float_as_uint(Bs[(k0 + gc) * PB + n]);
                bf[nf][1] = __float_as_uint(Bs[(k0 + 4 + gc) * PB + n]);
            }
            const int row = wm * 16 + gr;
            #pragma unroll
            for (int pass = 0; pass < 2; ++pass) {
                const float* Ap = pass ? Al : Ah;
                uint32_t a[4];
                a[0] = __float_as_uint(Ap[row * PA + k0 + gc]);
                a[1] = __float_as_uint(Ap[(row + 8) * PA + k0 + gc]);
                a[2] = __float_as_uint(Ap[row * PA + k0 + gc + 4]);
                a[3] = __float_as_uint(Ap[(row + 8) * PA + k0 + gc + 4]);
                #pragma unroll
                for (int nf = 0; nf < 8; ++nf) mma8(acc[nf], a, bf[nf]);
            }
        }
        __syncthreads();
    }

    // epilogue
    {
        size_t r0 = (size_t)(m0 + wm * 16 + gr);
        #pragma unroll
        for (int nf = 0; nf < 8; ++nf) {
            int col = wn * 64 + nf * 8 + 2 * gc;
            float4 v = acc[nf];
            *(float2*)&C[r0 * HD + col]       = make_float2(v.x, v.y);
            *(float2*)&C[(r0 + 8) * HD + col] = make_float2(v.z, v.w);
        }
    }
}

// ---------------------------------------------------------------------------
// Flash attention, tf32 mma.sync, fixed-offset softmax.
// 512 threads, 16 warps = 8 m-slabs x 2 kv-halves (wn). BQ=128, BKV=64,
// kv range additionally split in 2 block-halves (h). O/l partials by (h,wn).
// Q staged once in fragment-major XOR-swizzled panel -> LDS.128 per A-frag.
// ---------------------------------------------------------------------------
#define PK 132    // K/V smem row stride
#define PP 68     // P smem row stride
#define SQ_QP 0                       // Qperm: 16384 floats (64KB)
#define SQ_K  16384                   // Ks: 64*132
#define SQ_V  (SQ_K + 64*PK)          // Vs: 64*132
#define SQ_P  (SQ_V + 64*PK)          // Ps: 128*68
#define ATT_SMEM ((SQ_P + 128*PP) * 4)   // 167936 B

__global__ __launch_bounds__(512, 1)
void attn_mma(void)
{
    extern __shared__ float sm[];
    float* Qp = sm + SQ_QP;
    float* Ks = sm + SQ_K;
    float* Vs = sm + SQ_V;
    float* Ps = sm + SQ_P;

    const int tid  = threadIdx.x;
    const int lane = tid & 31, wid = tid >> 5;
    const int gr = lane >> 2, gc = lane & 3;
    const int wm = wid & 7, wn = wid >> 3;

    const int qt = (NQT - 1) - (blockIdx.x >> 1);   // heavy first
    const int h  = blockIdx.x & 1;
    const int b  = blockIdx.y;
    const int nkv = 2 * qt + 2;
    const int kt0 = h ? (nkv >> 1) : 0;
    const int kt1 = h ? nkv : (nkv >> 1);

    // ---- stage Q into fragment-major XOR-swizzled panel ----
    // layout: [wmq 8][ks 16][gr 8][gc 4][e 4] floats, byte ^= (ks&7)<<4
    {
        const float4* Qg = (const float4*)&g_Q[((size_t)b * SEQ + qt * 128) * HD];
        #pragma unroll
        for (int t = 0; t < 8; ++t) {
            int idx = tid + t * 512;
            int c4 = (idx & 15) | ((idx >> 11) << 4);
            int r  = (idx >> 4) & 127;
            float4 v = Qg[r * 32 + c4];
            float vv[4] = { tf32f(v.x), tf32f(v.y), tf32f(v.z), tf32f(v.w) };
            int wmq = r >> 4, grq = r & 7, i2 = (r >> 3) & 1;
            int ks = c4 >> 1, j = c4 & 1;
            #pragma unroll
            for (int m = 0; m < 4; ++m) {
                int fl = (((wmq * 16 + ks) * 8 + grq) * 4 + m) * 4 + 2 * j + i2;
                uint32_t byte = (uint32_t)(fl * 4) ^ (uint32_t)((ks & 7) << 4);
                *(float*)((char*)Qp + byte) = vv[m];
            }
        }
    }
    __syncthreads();

    float4 oacc[16];
    #pragma unroll
    for (int j = 0; j < 16; ++j) oacc[j] = make_float4(0.f, 0.f, 0.f, 0.f);
    float lrow0 = 0.f, lrow1 = 0.f;

    const int qrow = qt * 128 + wm * 16 + gr;   // global q row (and +8)
    const int prow = wm * 16 + gr;
    const int nb   = wn * 32;                   // this warp's kv column base in tile

    for (int kt = kt0; kt < kt1; ++kt) {
        // ---- load K/V tiles (tf32-rounded) ----
        const float* Kg = &g_K[((size_t)b * SEQ + kt * 64) * HD];
        const float* Vg = &g_V[((size_t)b * SEQ + kt * 64) * HD];
        #pragma unroll
        for (int t = 0; t < 4; ++t) {
            int i = tid + t * 512;
            int r = i >> 5, c4 = i & 31;
            float4 k4 = *(const float4*)&Kg[(size_t)r * HD + c4 * 4];
            k4.x = tf32f(k4.x); k4.y = tf32f(k4.y); k4.z = tf32f(k4.z); k4.w = tf32f(k4.w);
            *(float4*)&Ks[r * PK + c4 * 4] = k4;
            float4 v4 = *(const float4*)&Vg[(size_t)r * HD + c4 * 4];
            v4.x = tf32f(v4.x); v4.y = tf32f(v4.y); v4.z = tf32f(v4.z); v4.w = tf32f(v4.w);
            *(float4*)&Vs[r * PK + c4 * 4] = v4;
        }
        __syncthreads();

        // ---- S = Q K^T : per-warp m16 slab x n32 (wn half), K=128 ----
        float4 sacc[4];
        #pragma unroll
        for (int j = 0; j < 4; ++j) sacc[j] = make_float4(0.f, 0.f, 0.f, 0.f);
        #pragma unroll
        for (int ks = 0; ks < 16; ++ks) {
            int fl = (((wm * 16 + ks) * 8 + gr) * 4 + gc) * 4;
            uint32_t byte = (uint32_t)(fl * 4) ^ (uint32_t)((ks & 7) << 4);
            float4 qv = *(const float4*)((const char*)Qp + byte);
            uint32_t qa[4] = { __float_as_uint(qv.x), __float_as_uint(qv.y),
                               __float_as_uint(qv.z), __float_as_uint(qv.w) };
            const int k0 = ks * 8;
            #pragma unroll
            for (int nf = 0; nf < 4; ++nf) {
                uint32_t bb[2];
                bb[0] = __float_as_uint(Ks[(nb + nf * 8 + gr) * PK + k0 + gc]);
                bb[1] = __float_as_uint(Ks[(nb + nf * 8 + gr) * PK + k0 + 4 + gc]);
                mma8(sacc[nf], qa, bb);
            }
        }

        // ---- softmax (fixed offset) + P store ----
        const int kvb = kt * 64 + nb;
        #pragma unroll
        for (int nf = 0; nf < 4; ++nf) {
            int c = kvb + nf * 8 + 2 * gc;
            float4 s = sacc[nf];
            float e0 = (c     <= qrow)     ? __expf(s.x * SCALE) : 0.f;
            float e1 = (c + 1 <= qrow)     ? __expf(s.y * SCALE) : 0.f;
            float e2 = (c     <= qrow + 8) ? __expf(s.z * SCALE) : 0.f;
            float e3 = (c + 1 <= qrow + 8) ? __expf(s.w * SCALE) : 0.f;
            lrow0 += e0 + e1;
            lrow1 += e2 + e3;
            *(float2*)&Ps[prow * PP + nb + nf * 8 + 2 * gc] =
                make_float2(__uint_as_float(tf32r(e0)), __uint_as_float(tf32r(e1)));
            *(float2*)&Ps[(prow + 8) * PP + nb + nf * 8 + 2 * gc] =
                make_float2(__uint_as_float(tf32r(e2)), __uint_as_float(tf32r(e3)));
        }
        __syncwarp();

        // ---- O += P V : per-warp m16 slab x n128, K = wn's 32 kv ----
        #pragma unroll
        for (int ks = 0; ks < 4; ++ks) {
            const int k0 = nb + ks * 8;
            uint32_t a[4];
            a[0] = __float_as_uint(Ps[prow * PP + k0 + gc]);
            a[1] = __float_as_uint(Ps[(prow + 8) * PP + k0 + gc]);
            a[2] = __float_as_uint(Ps[prow * PP + k0 + gc + 4]);
            a[3] = __float_as_uint(Ps[(prow + 8) * PP + k0 + gc + 4]);
            #pragma unroll
            for (int nf = 0; nf < 16; ++nf) {
                uint32_t bb[2];
                bb[0] = __float_as_uint(Vs[(k0 + gc) * PK + nf * 8 + gr]);
                bb[1] = __float_as_uint(Vs[(k0 + 4 + gc) * PK + nf * 8 + gr]);
                mma8(oacc[nf], a, bb);
            }
        }
        __syncthreads();   // Ks/Vs/Ps reads done before next-iter overwrite
    }

    // ---- l reduce across the 4 lanes of each row group ----
    lrow0 += __shfl_xor_sync(0xffffffffu, lrow0, 1);
    lrow0 += __shfl_xor_sync(0xffffffffu, lrow0, 2);
    lrow1 += __shfl_xor_sync(0xffffffffu, lrow1, 1);
    lrow1 += __shfl_xor_sync(0xffffffffu, lrow1, 2);

    // ---- write unnormalized partials for (h, wn) ----
    const int part = h * 2 + wn;
    const size_t row0 = (size_t)b * SEQ + qt * 128 + wm * 16 + gr;
    float* Op = g_Op4[part];
    #pragma unroll
    for (int nf = 0; nf < 16; ++nf) {
        int col = nf * 8 + 2 * gc;
        float4 v = oacc[nf];
        *(float2*)&Op[row0 * HD + col]       = make_float2(v.x, v.y);
        *(float2*)&Op[(row0 + 8) * HD + col] = make_float2(v.z, v.w);
    }
    if (gc == 0) {
        g_lp4[part][row0]     = lrow0;
        g_lp4[part][row0 + 8] = lrow1;
    }
}

// ---------------------------------------------------------------------------
__global__ __launch_bounds__(256)
void combine_kernel(float* __restrict__ out)
{
    int idx = blockIdx.x * 256 + threadIdx.x;   // over 16384*32 float4
    int row = idx >> 5;
    float inv = 1.f / (g_lp4[0][row] + g_lp4[1][row] + g_lp4[2][row] + g_lp4[3][row]);
    float4 a = ((const float4*)g_Op4[0])[idx];
    float4 c = ((const float4*)g_Op4[1])[idx];
    float4 d = ((const float4*)g_Op4[2])[idx];
    float4 e = ((const float4*)g_Op4[3])[idx];
    ((float4*)out)[idx] = make_float4((a.x + c.x + d.x + e.x) * inv,
                                      (a.y + c.y + d.y + e.y) * inv,
                                      (a.z + c.z + d.z + e.z) * inv,
                                      (a.w + c.w + d.w + e.w) * inv);
}

// ---------------------------------------------------------------------------
extern "C" void kernel_launch(void* const* d_in, const int* in_sizes, int n_in,
                              void* d_out, int out_size)
{
    const float* x  = (const float*)d_in[0];
    const float* Wq = (const float*)d_in[1];
    const float* Wk = (const float*)d_in[2];
    const float* Wv = (const float*)d_in[3];
    float* out = (float*)d_out;

    cudaFuncSetAttribute(qkv_mma, cudaFuncAttributeMaxDynamicSharedMemorySize, PROJ_SMEM);
    cudaFuncSetAttribute(attn_mma, cudaFuncAttributeMaxDynamicSharedMemorySize, ATT_SMEM);

    qkv_mma<<<dim3(128, 3), 512, PROJ_SMEM>>>(x, Wq, Wk, Wv);
    attn_mma<<<dim3(2 * NQT, BATCH), 512, ATT_SMEM>>>();
    combine_kernel<<<(BATCH * SEQ * HD / 4) / 256, 256>>>(out);
}

// round 8
// speedup vs baseline: 2.3436x; 2.3436x over previous
#include <cuda_runtime.h>
#include <cuda_fp16.h>
#include <cstdint>

#define SEQ   4096
#define DM    1024
#define HD    128
#define BATCH 4
#define NQT   32          // SEQ / 128
#define SCALE 0.08838834764831845f

__device__ __half g_Q[BATCH*SEQ*HD];
__device__ __half g_K[BATCH*SEQ*HD];
__device__ __half g_V[BATCH*SEQ*HD];
__device__ float  g_Op[2][BATCH*SEQ*HD];
__device__ float  g_lp[2][BATCH*SEQ];

// ---------------- helpers ----------------
__device__ __forceinline__ uint32_t smem_u32(const void* p) {
    uint32_t a;
    asm("{ .reg .u64 t; cvta.to.shared.u64 t, %1; cvt.u32.u64 %0, t; }" : "=r"(a) : "l"(p));
    return a;
}
__device__ __forceinline__ void ldsm4(uint32_t* r, uint32_t a) {
    asm volatile("ldmatrix.sync.aligned.m8n8.x4.shared.b16 {%0,%1,%2,%3}, [%4];"
        : "=r"(r[0]), "=r"(r[1]), "=r"(r[2]), "=r"(r[3]) : "r"(a));
}
__device__ __forceinline__ void ldsm4t(uint32_t* r, uint32_t a) {
    asm volatile("ldmatrix.sync.aligned.m8n8.x4.trans.shared.b16 {%0,%1,%2,%3}, [%4];"
        : "=r"(r[0]), "=r"(r[1]), "=r"(r[2]), "=r"(r[3]) : "r"(a));
}
__device__ __forceinline__ void mma16(float4& d, const uint32_t a[4], const uint32_t b[2]) {
    asm volatile(
        "mma.sync.aligned.m16n8k16.row.col.f32.f16.f16.f32 "
        "{%0,%1,%2,%3}, {%4,%5,%6,%7}, {%8,%9}, {%0,%1,%2,%3};"
        : "+f"(d.x), "+f"(d.y), "+f"(d.z), "+f"(d.w)
        : "r"(a[0]), "r"(a[1]), "r"(a[2]), "r"(a[3]), "r"(b[0]), "r"(b[1]));
}

// ---------------------------------------------------------------------------
// QKV projection: C[16384,128] = x[16384,1024] @ W[1024,128], fp16 in, f32 acc.
// 256 threads, 8 warps (4m x 2n), warp tile 32x64, K chunk 32.
// A: [128 rows][32 k] halfs, stride 40. Bt (W transposed): [128 n][32 k], stride 40.
// ---------------------------------------------------------------------------
#define SA 40
#define PROJ_SMEM ((128*SA + 128*SA) * 2)   // 20480 B

__global__ __launch_bounds__(256, 2)
void qkv_mma(const float* __restrict__ x,
             const float* __restrict__ Wq,
             const float* __restrict__ Wk,
             const float* __restrict__ Wv)
{
    extern __shared__ __half smh[];
    __half* Ah = smh;                 // [128][40]
    __half* Bt = smh + 128 * SA;      // [128][40] (n-major, k contiguous)
    const uint32_t ah_b = smem_u32(Ah);
    const uint32_t bt_b = smem_u32(Bt);

    const int tid  = threadIdx.x;
    const int lane = tid & 31, wid = tid >> 5;
    const int gr = lane >> 2, gc = lane & 3;
    const int wm = wid & 3, wn = wid >> 2;

    const int wsel = blockIdx.y;
    const float* __restrict__ W = (wsel == 0) ? Wq : (wsel == 1) ? Wk : Wv;
    __half* __restrict__ C = (wsel == 0) ? g_Q : (wsel == 1) ? g_K : g_V;
    const int m0 = blockIdx.x * 128;

    // ldmatrix lane-address components
    const int lrow  = ((lane >> 3) & 1) * 8 + (lane & 7);  // A row / (t&1)
    const int lcolA = (lane >> 4) * 8;                     // A col / (t>>1)
    const int brow  = (lane >> 4) * 8 + (lane & 7);        // B n / (t>>1)
    const int bcol  = ((lane >> 3) & 1) * 8;               // B k / (t&1)

    float4 acc[2][8];
    #pragma unroll
    for (int i = 0; i < 2; i++)
        #pragma unroll
        for (int j = 0; j < 8; j++) acc[i][j] = make_float4(0.f, 0.f, 0.f, 0.f);

    float4 ra[4];
    float2 rb[8];
    // prefetch chunk 0
    #pragma unroll
    for (int t = 0; t < 4; ++t) {
        int i = tid + t * 256;
        int r = i >> 3, c4 = i & 7;
        ra[t] = *(const float4*)&x[(size_t)(m0 + r) * DM + c4 * 4];
    }
    #pragma unroll
    for (int t = 0; t < 8; ++t) {
        int n = tid & 127;
        int k = t * 4 + (tid >> 7) * 2;
        rb[t].x = W[(size_t)k * HD + n];
        rb[t].y = W[(size_t)(k + 1) * HD + n];
    }

    for (int kc = 0; kc < 32; ++kc) {
        // regs -> smem (convert to fp16)
        #pragma unroll
        for (int t = 0; t < 4; ++t) {
            int i = tid + t * 256;
            int r = i >> 3, c4 = i & 7;
            __half2 h0 = __floats2half2_rn(ra[t].x, ra[t].y);
            __half2 h1 = __floats2half2_rn(ra[t].z, ra[t].w);
            *(__half2*)&Ah[r * SA + c4 * 4]     = h0;
            *(__half2*)&Ah[r * SA + c4 * 4 + 2] = h1;
        }
        #pragma unroll
        for (int t = 0; t < 8; ++t) {
            int n = tid & 127;
            int k = t * 4 + (tid >> 7) * 2;
            *(__half2*)&Bt[n * SA + k] = __floats2half2_rn(rb[t].x, rb[t].y);
        }
        __syncthreads();
        if (kc < 31) {   // prefetch next chunk
            #pragma unroll
            for (int t = 0; t < 4; ++t) {
                int i = tid + t * 256;
                int r = i >> 3, c4 = i & 7;
                ra[t] = *(const float4*)&x[(size_t)(m0 + r) * DM + (kc + 1) * 32 + c4 * 4];
            }
            #pragma unroll
            for (int t = 0; t < 8; ++t) {
                int n = tid & 127;
                int k = (kc + 1) * 32 + t * 4 + (tid >> 7) * 2;
                rb[t].x = W[(size_t)k * HD + n];
                rb[t].y = W[(size_t)(k + 1) * HD + n];
            }
        }
        #pragma unroll
        for (int ks = 0; ks < 2; ++ks) {
            const int k0 = ks * 16;
            uint32_t af[2][4];
            #pragma unroll
            for (int mf = 0; mf < 2; ++mf) {
                int row0 = wm * 32 + mf * 16;
                ldsm4(af[mf], ah_b + (uint32_t)(((row0 + lrow) * SA + k0 + lcolA) * 2));
            }
            #pragma unroll
            for (int p = 0; p < 4; ++p) {
                int n0 = wn * 64 + p * 16;
                uint32_t bf[4];
                ldsm4(bf, bt_b + (uint32_t)(((n0 + brow) * SA + k0 + bcol) * 2));
                #pragma unroll
                for (int mf = 0; mf < 2; ++mf) {
                    mma16(acc[mf][2 * p],     af[mf], bf);
                    mma16(acc[mf][2 * p + 1], af[mf], bf + 2);
                }
            }
        }
        __syncthreads();
    }

    // epilogue: fp16 out
    #pragma unroll
    for (int mf = 0; mf < 2; ++mf) {
        size_t r0 = (size_t)(m0 + wm * 32 + mf * 16 + gr);
        #pragma unroll
        for (int nf = 0; nf < 8; ++nf) {
            int col = wn * 64 + nf * 8 + 2 * gc;
            float4 v = acc[mf][nf];
            *(__half2*)&C[r0 * HD + col]       = __floats2half2_rn(v.x, v.y);
            *(__half2*)&C[(r0 + 8) * HD + col] = __floats2half2_rn(v.z, v.w);
        }
    }
}

// ---------------------------------------------------------------------------
// Flash attention, fp16 mma.sync m16n8k16 + ldmatrix, fixed-offset softmax.
// 256 threads, 8 warps = 8 m16 slabs. BQ=128, BKV=64, kv split in 2 halves (h).
// ---------------------------------------------------------------------------
#define SQ 136    // Q/K/V smem row stride (halfs)
#define SP 72     // P smem row stride (halfs)
#define N_QS (128*SQ)
#define N_KS (64*SQ)
#define ATT_SMEM ((N_QS + 2*N_KS + 128*SP) * 2)   // 88064 B

__global__ __launch_bounds__(256, 2)
void attn_mma(void)
{
    extern __shared__ __half smh[];
    __half* Qs = smh;
    __half* Ks = Qs + N_QS;
    __half* Vs = Ks + N_KS;
    __half* Ps = Vs + N_KS;
    const uint32_t qs_b = smem_u32(Qs);
    const uint32_t ks_b = smem_u32(Ks);
    const uint32_t vs_b = smem_u32(Vs);
    const uint32_t ps_b = smem_u32(Ps);

    const int tid  = threadIdx.x;
    const int lane = tid & 31, wid = tid >> 5;
    const int gr = lane >> 2, gc = lane & 3;

    const int qt = (NQT - 1) - (blockIdx.x >> 1);   // heavy first
    const int h  = blockIdx.x & 1;
    const int b  = blockIdx.y;
    const int nkv = 2 * qt + 2;
    const int kt0 = h ? (nkv >> 1) : 0;
    const int kt1 = h ? nkv : (nkv >> 1);

    // ldmatrix lane-address components
    const int lrow  = ((lane >> 3) & 1) * 8 + (lane & 7);
    const int lcolA = (lane >> 4) * 8;
    const int brow  = (lane >> 4) * 8 + (lane & 7);
    const int bcol  = ((lane >> 3) & 1) * 8;

    // ---- stage Q (fp16 copy) ----
    {
        const uint4* Qg = (const uint4*)&g_Q[((size_t)b * SEQ + qt * 128) * HD];
        #pragma unroll
        for (int t = 0; t < 8; ++t) {
            int i = tid + t * 256;
            int r = i >> 4, cq = i & 15;
            *(uint4*)&Qs[r * SQ + cq * 8] = Qg[r * 16 + cq];
        }
    }
    __syncthreads();

    float4 oacc[16];
    #pragma unroll
    for (int j = 0; j < 16; ++j) oacc[j] = make_float4(0.f, 0.f, 0.f, 0.f);
    float lrow0 = 0.f, lrow1 = 0.f;

    const int row0 = wid * 16;
    const int qrow = qt * 128 + row0 + gr;   // global q row (and +8)
    const int prow = row0 + gr;

    for (int kt = kt0; kt < kt1; ++kt) {
        // ---- stage K/V tiles (fp16 copy) ----
        const uint4* Kg = (const uint4*)&g_K[((size_t)b * SEQ + kt * 64) * HD];
        const uint4* Vg = (const uint4*)&g_V[((size_t)b * SEQ + kt * 64) * HD];
        #pragma unroll
        for (int t = 0; t < 4; ++t) {
            int i = tid + t * 256;
            int r = i >> 4, cq = i & 15;
            *(uint4*)&Ks[r * SQ + cq * 8] = Kg[r * 16 + cq];
            *(uint4*)&Vs[r * SQ + cq * 8] = Vg[r * 16 + cq];
        }
        __syncthreads();

        // ---- S = Q K^T in two n32 halves; softmax; P store ----
        #pragma unroll
        for (int h2 = 0; h2 < 2; ++h2) {
            float4 sacc[4];
            #pragma unroll
            for (int j = 0; j < 4; ++j) sacc[j] = make_float4(0.f, 0.f, 0.f, 0.f);
            #pragma unroll
            for (int ks = 0; ks < 8; ++ks) {
                const int k0 = ks * 16;
                uint32_t qa[4];
                ldsm4(qa, qs_b + (uint32_t)(((row0 + lrow) * SQ + k0 + lcolA) * 2));
                #pragma unroll
                for (int p = 0; p < 2; ++p) {
                    int n0 = h2 * 32 + p * 16;
                    uint32_t bf[4];
                    ldsm4(bf, ks_b + (uint32_t)(((n0 + brow) * SQ + k0 + bcol) * 2));
                    mma16(sacc[2 * p],     qa, bf);
                    mma16(sacc[2 * p + 1], qa, bf + 2);
                }
            }
            // softmax (fixed offset) + P store
            const int kvb = kt * 64 + h2 * 32;
            #pragma unroll
            for (int nf = 0; nf < 4; ++nf) {
                int c = kvb + nf * 8 + 2 * gc;
                float4 s = sacc[nf];
                float e0 = (c     <= qrow)     ? __expf(s.x * SCALE) : 0.f;
                float e1 = (c + 1 <= qrow)     ? __expf(s.y * SCALE) : 0.f;
                float e2 = (c     <= qrow + 8) ? __expf(s.z * SCALE) : 0.f;
                float e3 = (c + 1 <= qrow + 8) ? __expf(s.w * SCALE) : 0.f;
                lrow0 += e0 + e1;
                lrow1 += e2 + e3;
                *(__half2*)&Ps[prow * SP + h2 * 32 + nf * 8 + 2 * gc] =
                    __floats2half2_rn(e0, e1);
                *(__half2*)&Ps[(prow + 8) * SP + h2 * 32 + nf * 8 + 2 * gc] =
                    __floats2half2_rn(e2, e3);
            }
        }
        __syncwarp();

        // ---- O += P V : m16 slab x n128, K=64 ----
        #pragma unroll
        for (int ks = 0; ks < 4; ++ks) {
            const int k0 = ks * 16;
            uint32_t pa[4];
            ldsm4(pa, ps_b + (uint32_t)(((row0 + lrow) * SP + k0 + lcolA) * 2));
            #pragma unroll
            for (int p = 0; p < 8; ++p) {
                int n0 = p * 16;
                uint32_t vb[4];
                // trans: rows are kv (k), cols are hd (n)
                ldsm4t(vb, vs_b + (uint32_t)(((k0 + lrow) * SQ + n0 + lcolA) * 2));
                mma16(oacc[2 * p],     pa, vb);
                mma16(oacc[2 * p + 1], pa, vb + 2);
            }
        }
        __syncthreads();   // Ks/Vs reads done before next-iter overwrite
    }

    // ---- l reduce across the 4 lanes of each row group ----
    lrow0 += __shfl_xor_sync(0xffffffffu, lrow0, 1);
    lrow0 += __shfl_xor_sync(0xffffffffu, lrow0, 2);
    lrow1 += __shfl_xor_sync(0xffffffffu, lrow1, 1);
    lrow1 += __shfl_xor_sync(0xffffffffu, lrow1, 2);

    // ---- write unnormalized partials ----
    const size_t grow0 = (size_t)b * SEQ + qt * 128 + row0 + gr;
    float* Op = g_Op[h];
    #pragma unroll
    for (int nf = 0; nf < 16; ++nf) {
        int col = nf * 8 + 2 * gc;
        float4 v = oacc[nf];
        *(float2*)&Op[grow0 * HD + col]       = make_float2(v.x, v.y);
        *(float2*)&Op[(grow0 + 8) * HD + col] = make_float2(v.z, v.w);
    }
    if (gc == 0) {
        g_lp[h][grow0]     = lrow0;
        g_lp[h][grow0 + 8] = lrow1;
    }
}

// ---------------------------------------------------------------------------
__global__ __launch_bounds__(256)
void combine_kernel(float* __restrict__ out)
{
    int idx = blockIdx.x * 256 + threadIdx.x;   // over 16384*32 float4
    int row = idx >> 5;
    float inv = 1.f / (g_lp[0][row] + g_lp[1][row]);
    float4 a = ((const float4*)g_Op[0])[idx];
    float4 c = ((const float4*)g_Op[1])[idx];
    ((float4*)out)[idx] = make_float4((a.x + c.x) * inv, (a.y + c.y) * inv,
                                      (a.z + c.z) * inv, (a.w + c.w) * inv);
}

// ---------------------------------------------------------------------------
extern "C" void kernel_launch(void* const* d_in, const int* in_sizes, int n_in,
                              void* d_out, int out_size)
{
    const float* x  = (const float*)d_in[0];
    const float* Wq = (const float*)d_in[1];
    const float* Wk = (const float*)d_in[2];
    const float* Wv = (const float*)d_in[3];
    float* out = (float*)d_out;

    cudaFuncSetAttribute(qkv_mma, cudaFuncAttributeMaxDynamicSharedMemorySize, PROJ_SMEM);
    cudaFuncSetAttribute(attn_mma, cudaFuncAttributeMaxDynamicSharedMemorySize, ATT_SMEM);

    qkv_mma<<<dim3(128, 3), 256, PROJ_SMEM>>>(x, Wq, Wk, Wv);
    attn_mma<<<dim3(2 * NQT, BATCH), 256, ATT_SMEM>>>();
    combine_kernel<<<(BATCH * SEQ * HD / 4) / 256, 256>>>(out);
}

// round 11
// speedup vs baseline: 2.9610x; 1.2634x over previous
#include <cuda_runtime.h>
#include <cuda_fp16.h>
#include <cstdint>

#define SEQ   4096
#define DM    1024
#define HD    128
#define BATCH 4
#define NQT   32          // SEQ / 128
#define SCALE 0.08838834764831845f

__device__ __half g_xh[BATCH*SEQ*DM];
__device__ __half g_Wh[3*DM*HD];
__device__ __half g_Q[BATCH*SEQ*HD];
__device__ __half g_K[BATCH*SEQ*HD];
__device__ __half g_V[BATCH*SEQ*HD];
__device__ float  g_Op4[4][BATCH*SEQ*HD];
__device__ float  g_lp4[4][BATCH*SEQ];

// ---------------- helpers ----------------
__device__ __forceinline__ uint32_t smem_u32(const void* p) {
    uint32_t a;
    asm("{ .reg .u64 t; cvta.to.shared.u64 t, %1; cvt.u32.u64 %0, t; }" : "=r"(a) : "l"(p));
    return a;
}
__device__ __forceinline__ void ldsm4(uint32_t* r, uint32_t a) {
    asm volatile("ldmatrix.sync.aligned.m8n8.x4.shared.b16 {%0,%1,%2,%3}, [%4];"
        : "=r"(r[0]), "=r"(r[1]), "=r"(r[2]), "=r"(r[3]) : "r"(a));
}
__device__ __forceinline__ void ldsm4t(uint32_t* r, uint32_t a) {
    asm volatile("ldmatrix.sync.aligned.m8n8.x4.trans.shared.b16 {%0,%1,%2,%3}, [%4];"
        : "=r"(r[0]), "=r"(r[1]), "=r"(r[2]), "=r"(r[3]) : "r"(a));
}
__device__ __forceinline__ void mma16(float4& d, const uint32_t a[4], const uint32_t b[2]) {
    asm volatile(
        "mma.sync.aligned.m16n8k16.row.col.f32.f16.f16.f32 "
        "{%0,%1,%2,%3}, {%4,%5,%6,%7}, {%8,%9}, {%0,%1,%2,%3};"
        : "+f"(d.x), "+f"(d.y), "+f"(d.z), "+f"(d.w)
        : "r"(a[0]), "r"(a[1]), "r"(a[2]), "r"(a[3]), "r"(b[0]), "r"(b[1]));
}
__device__ __forceinline__ void cp16(uint32_t s, const void* g) {
    asm volatile("cp.async.cg.shared.global [%0], [%1], 16;" :: "r"(s), "l"(g));
}
#define CP_COMMIT() asm volatile("cp.async.commit_group;" ::: "memory")
template<int N> __device__ __forceinline__ void cp_wait() {
    asm volatile("cp.async.wait_group %0;" :: "n"(N) : "memory");
}
__device__ __forceinline__ uint32_t packh2(float a, float b) {
    __half2 h = __floats2half2_rn(a, b);
    return *(uint32_t*)&h;
}

// ---------------------------------------------------------------------------
// Prepass: x (fp32) -> g_xh (fp16), Wq/Wk/Wv -> g_Wh
// ---------------------------------------------------------------------------
#define X_F4 (BATCH*SEQ*DM/4)      // 4194304
#define W_F4 (DM*HD/4)             // 32768
#define CVT_BLOCKS ((X_F4 + 3*W_F4) / 1024)   // 4192

__global__ __launch_bounds__(256)
void cvt_kernel(const float* __restrict__ x, const float* __restrict__ Wq,
                const float* __restrict__ Wk, const float* __restrict__ Wv)
{
    int i = blockIdx.x * 1024 + threadIdx.x;
    #pragma unroll
    for (int j = 0; j < 4; ++j, i += 256) {
        float4 v;
        __half* dst;
        if (i < X_F4) {
            v = ((const float4*)x)[i];
            dst = g_xh + (size_t)i * 4;
        } else {
            int wi = i - X_F4;
            int ws = wi >> 15, off = wi & 32767;
            const float* W = (ws == 0) ? Wq : (ws == 1) ? Wk : Wv;
            v = ((const float4*)W)[off];
            dst = g_Wh + (size_t)ws * (DM * HD) + (size_t)off * 4;
        }
        *(__half2*)dst       = __floats2half2_rn(v.x, v.y);
        *(__half2*)(dst + 2) = __floats2half2_rn(v.z, v.w);
    }
}

// ---------------------------------------------------------------------------
// QKV projection: C[16384,128] = xh @ Wh[wsel], fp16 mma + cp.async double buffer.
// 256 threads, 8 warps (4m x 2n), warp tile 32x64, K chunk 32.
// A: [128 m][32 k] stride 40 halfs. B: [32 k][128 n] stride 136 halfs (ldsm trans).
// ---------------------------------------------------------------------------
#define QA_H (128*40)              // halfs per A buffer
#define QB_H (32*136)
#define PROJ_SMEM ((2*QA_H + 2*QB_H) * 2)   // 37888 B

__global__ __launch_bounds__(256, 2)
void qkv_mma(void)
{
    extern __shared__ __half smh[];
    const uint32_t a_b = smem_u32(smh);                 // A[2]
    const uint32_t b_b = a_b + 2 * QA_H * 2;            // B[2]

    const int tid  = threadIdx.x;
    const int lane = tid & 31, wid = tid >> 5;
    const int gr = lane >> 2, gc = lane & 3;
    const int wm = wid & 3, wn = wid >> 2;

    const int wsel = blockIdx.y;
    const __half* __restrict__ Wh = g_Wh + (size_t)wsel * (DM * HD);
    __half* __restrict__ C = (wsel == 0) ? g_Q : (wsel == 1) ? g_K : g_V;
    const int m0 = blockIdx.x * 128;

    const int lrow  = ((lane >> 3) & 1) * 8 + (lane & 7);
    const int lcolA = (lane >> 4) * 8;

    float4 acc[2][8];
    #pragma unroll
    for (int i = 0; i < 2; i++)
        #pragma unroll
        for (int j = 0; j < 8; j++) acc[i][j] = make_float4(0.f, 0.f, 0.f, 0.f);

    auto issue = [&](int kc, int bsel) {
        uint32_t as = a_b + bsel * QA_H * 2;
        uint32_t bs = b_b + bsel * QB_H * 2;
        #pragma unroll
        for (int t = 0; t < 2; ++t) {       // A: 512 x 16B
            int i = tid + t * 256;
            int r = i >> 2, u = i & 3;
            cp16(as + (uint32_t)((r * 40 + u * 8) * 2),
                 g_xh + ((size_t)(m0 + r)) * DM + kc * 32 + u * 8);
        }
        #pragma unroll
        for (int t = 0; t < 2; ++t) {       // B: 512 x 16B
            int i = tid + t * 256;
            int r = i >> 4, u = i & 15;
            cp16(bs + (uint32_t)((r * 136 + u * 8) * 2),
                 Wh + (size_t)(kc * 32 + r) * HD + u * 8);
        }
    };

    int buf = 0;
    issue(0, 0); CP_COMMIT();
    for (int kc = 0; kc < 32; ++kc) {
        if (kc < 31) { issue(kc + 1, buf ^ 1); CP_COMMIT(); cp_wait<1>(); }
        else         { cp_wait<0>(); }
        __syncthreads();
        uint32_t as = a_b + buf * QA_H * 2;
        uint32_t bs = b_b + buf * QB_H * 2;
        #pragma unroll
        for (int ks = 0; ks < 2; ++ks) {
            const int k0 = ks * 16;
            uint32_t af[2][4];
            ldsm4(af[0], as + (uint32_t)(((wm * 32 + lrow) * 40 + k0 + lcolA) * 2));
            ldsm4(af[1], as + (uint32_t)(((wm * 32 + 16 + lrow) * 40 + k0 + lcolA) * 2));
            #pragma unroll
            for (int p = 0; p < 4; ++p) {
                int n0 = wn * 64 + p * 16;
                uint32_t bf[4];
                ldsm4t(bf, bs + (uint32_t)(((k0 + lrow) * 136 + n0 + lcolA) * 2));
                #pragma unroll
                for (int mf = 0; mf < 2; ++mf) {
                    mma16(acc[mf][2 * p],     af[mf], bf);
                    mma16(acc[mf][2 * p + 1], af[mf], bf + 2);
                }
            }
        }
        __syncthreads();
        buf ^= 1;
    }

    #pragma unroll
    for (int mf = 0; mf < 2; ++mf) {
        size_t r0 = (size_t)(m0 + wm * 32 + mf * 16 + gr);
        #pragma unroll
        for (int nf = 0; nf < 8; ++nf) {
            int col = wn * 64 + nf * 8 + 2 * gc;
            float4 v = acc[mf][nf];
            *(__half2*)&C[r0 * HD + col]       = __floats2half2_rn(v.x, v.y);
            *(__half2*)&C[(r0 + 8) * HD + col] = __floats2half2_rn(v.z, v.w);
        }
    }
}

// ---------------------------------------------------------------------------
// Flash attention: 128 threads, 4 warps x m32 slabs, P in registers,
// cp.async double-buffered K/V, kv range split 4 ways per (b,qt).
// ---------------------------------------------------------------------------
#define SQ 136
#define NQ_H (128*SQ)
#define NK_H (64*SQ)
#define ATT_SMEM ((NQ_H + 4*NK_H) * 2)    // 104448 B

__global__ __launch_bounds__(128, 2)
void attn_mma(void)
{
    extern __shared__ __half smh[];
    const uint32_t qs_b = smem_u32(smh);
    const uint32_t kv_b = qs_b + NQ_H * 2;     // K[0],V[0],K[1],V[1]

    const int tid  = threadIdx.x;
    const int lane = tid & 31, wid = tid >> 5;
    const int gr = lane >> 2, gc = lane & 3;
    const int wr = wid * 32;

    const int qt   = (NQT - 1) - (blockIdx.x >> 2);   // heavy first
    const int part = blockIdx.x & 3;
    const int b    = blockIdx.y;
    const int nkv  = 2 * qt + 2;
    const int kt0  = (nkv * part) >> 2;
    const int kt1  = (nkv * (part + 1)) >> 2;

    const int lrow  = ((lane >> 3) & 1) * 8 + (lane & 7);
    const int lcolA = (lane >> 4) * 8;
    const int brow  = (lane >> 4) * 8 + (lane & 7);
    const int bcol  = ((lane >> 3) & 1) * 8;

    auto issue_kv = [&](int kt, int bsel) {
        uint32_t ks = kv_b + (2 * bsel) * NK_H * 2;
        uint32_t vs = ks + NK_H * 2;
        const __half* Kg = g_K + ((size_t)b * SEQ + kt * 64) * HD;
        const __half* Vg = g_V + ((size_t)b * SEQ + kt * 64) * HD;
        #pragma unroll
        for (int t = 0; t < 8; ++t) {
            int i = tid + t * 128;
            int r = i >> 4, u = i & 15;
            uint32_t so = (uint32_t)((r * SQ + u * 8) * 2);
            cp16(ks + so, Kg + (size_t)r * HD + u * 8);
            cp16(vs + so, Vg + (size_t)r * HD + u * 8);
        }
    };

    // prologue: Q + first KV
    {
        const __half* Qg = g_Q + ((size_t)b * SEQ + qt * 128) * HD;
        #pragma unroll
        for (int t = 0; t < 16; ++t) {
            int i = tid + t * 128;
            int r = i >> 4, u = i & 15;
            cp16(qs_b + (uint32_t)((r * SQ + u * 8) * 2), Qg + (size_t)r * HD + u * 8);
        }
        if (kt0 < kt1) issue_kv(kt0, 0);
        CP_COMMIT();
    }

    float4 oacc[2][16];
    #pragma unroll
    for (int mf = 0; mf < 2; ++mf)
        #pragma unroll
        for (int j = 0; j < 16; ++j) oacc[mf][j] = make_float4(0.f, 0.f, 0.f, 0.f);
    float lr[4] = {0.f, 0.f, 0.f, 0.f};

    const int qr0 = qt * 128 + wr + gr;   // rows qr0 + {0,8,16,24}

    int buf = 0;
    for (int kt = kt0; kt < kt1; ++kt) {
        if (kt + 1 < kt1) { issue_kv(kt + 1, buf ^ 1); CP_COMMIT(); cp_wait<1>(); }
        else              { cp_wait<0>(); }
        __syncthreads();
        const uint32_t kb = kv_b + (2 * buf) * NK_H * 2;
        const uint32_t vb_base = kb + NK_H * 2;

        uint32_t pf[2][8][2];
        // ---- S = Q K^T in two n32 halves; softmax into pf ----
        #pragma unroll
        for (int h2 = 0; h2 < 2; ++h2) {
            float4 s[2][4];
            #pragma unroll
            for (int mf = 0; mf < 2; ++mf)
                #pragma unroll
                for (int j = 0; j < 4; ++j) s[mf][j] = make_float4(0.f, 0.f, 0.f, 0.f);
            #pragma unroll
            for (int ks = 0; ks < 8; ++ks) {
                const int k0 = ks * 16;
                uint32_t af[2][4];
                ldsm4(af[0], qs_b + (uint32_t)(((wr + lrow) * SQ + k0 + lcolA) * 2));
                ldsm4(af[1], qs_b + (uint32_t)(((wr + 16 + lrow) * SQ + k0 + lcolA) * 2));
                #pragma unroll
                for (int p = 0; p < 2; ++p) {
                    int n0 = h2 * 32 + p * 16;
                    uint32_t bf[4];
                    ldsm4(bf, kb + (uint32_t)(((n0 + brow) * SQ + k0 + bcol) * 2));
                    #pragma unroll
                    for (int mf = 0; mf < 2; ++mf) {
                        mma16(s[mf][2 * p],     af[mf], bf);
                        mma16(s[mf][2 * p + 1], af[mf], bf + 2);
                    }
                }
            }
            const int kvb = kt * 64 + h2 * 32;
            #pragma unroll
            for (int mf = 0; mf < 2; ++mf) {
                const int r0 = qr0 + mf * 16, r1 = r0 + 8;
                #pragma unroll
                for (int nf = 0; nf < 4; ++nf) {
                    int c = kvb + nf * 8 + 2 * gc;
                    float4 sv = s[mf][nf];
                    float e0 = (c     <= r0) ? __expf(sv.x * SCALE) : 0.f;
                    float e1 = (c + 1 <= r0) ? __expf(sv.y * SCALE) : 0.f;
                    float e2 = (c     <= r1) ? __expf(sv.z * SCALE) : 0.f;
                    float e3 = (c + 1 <= r1) ? __expf(sv.w * SCALE) : 0.f;
                    lr[2 * mf]     += e0 + e1;
                    lr[2 * mf + 1] += e2 + e3;
                    pf[mf][h2 * 4 + nf][0] = packh2(e0, e1);
                    pf[mf][h2 * 4 + nf][1] = packh2(e2, e3);
                }
            }
        }

        // ---- O += P V : m32 x n128, K=64, P from registers ----
        #pragma unroll
        for (int ks = 0; ks < 4; ++ks) {
            #pragma unroll
            for (int p = 0; p < 8; ++p) {
                int n0 = p * 16;
                uint32_t vb[4];
                ldsm4t(vb, vb_base + (uint32_t)(((ks * 16 + lrow) * SQ + n0 + lcolA) * 2));
                #pragma unroll
                for (int mf = 0; mf < 2; ++mf) {
                    uint32_t pa[4] = { pf[mf][2 * ks][0], pf[mf][2 * ks][1],
                                       pf[mf][2 * ks + 1][0], pf[mf][2 * ks + 1][1] };
                    mma16(oacc[mf][2 * p],     pa, vb);
                    mma16(oacc[mf][2 * p + 1], pa, vb + 2);
                }
            }
        }
        __syncthreads();
        buf ^= 1;
    }
    cp_wait<0>();

    // ---- l reduce across the 4 gc lanes of each row group ----
    #pragma unroll
    for (int j = 0; j < 4; ++j) {
        lr[j] += __shfl_xor_sync(0xffffffffu, lr[j], 1);
        lr[j] += __shfl_xor_sync(0xffffffffu, lr[j], 2);
    }

    // ---- write unnormalized partials ----
    float* Op = g_Op4[part];
    float* lp = g_lp4[part];
    #pragma unroll
    for (int mf = 0; mf < 2; ++mf) {
        const size_t r0 = (size_t)b * SEQ + qt * 128 + wr + mf * 16 + gr;
        #pragma unroll
        for (int nf = 0; nf < 16; ++nf) {
            int col = nf * 8 + 2 * gc;
            float4 v = oacc[mf][nf];
            *(float2*)&Op[r0 * HD + col]       = make_float2(v.x, v.y);
            *(float2*)&Op[(r0 + 8) * HD + col] = make_float2(v.z, v.w);
        }
        if (gc == 0) {
            lp[r0]     = lr[2 * mf];
            lp[r0 + 8] = lr[2 * mf + 1];
        }
    }
}

// ---------------------------------------------------------------------------
__global__ __launch_bounds__(256)
void combine_kernel(float* __restrict__ out)
{
    int idx = blockIdx.x * 256 + threadIdx.x;   // over 16384*32 float4
    int row = idx >> 5;
    float inv = 1.f / (g_lp4[0][row] + g_lp4[1][row] + g_lp4[2][row] + g_lp4[3][row]);
    float4 a = ((const float4*)g_Op4[0])[idx];
    float4 c = ((const float4*)g_Op4[1])[idx];
    float4 d = ((const float4*)g_Op4[2])[idx];
    float4 e = ((const float4*)g_Op4[3])[idx];
    ((float4*)out)[idx] = make_float4((a.x + c.x + d.x + e.x) * inv,
                                      (a.y + c.y + d.y + e.y) * inv,
                                      (a.z + c.z + d.z + e.z) * inv,
                                      (a.w + c.w + d.w + e.w) * inv);
}

// ---------------------------------------------------------------------------
extern "C" void kernel_launch(void* const* d_in, const int* in_sizes, int n_in,
                              void* d_out, int out_size)
{
    const float* x  = (const float*)d_in[0];
    const float* Wq = (const float*)d_in[1];
    const float* Wk = (const float*)d_in[2];
    const float* Wv = (const float*)d_in[3];
    float* out = (float*)d_out;

    cudaFuncSetAttribute(qkv_mma, cudaFuncAttributeMaxDynamicSharedMemorySize, PROJ_SMEM);
    cudaFuncSetAttribute(attn_mma, cudaFuncAttributeMaxDynamicSharedMemorySize, ATT_SMEM);

    cvt_kernel<<<CVT_BLOCKS, 256>>>(x, Wq, Wk, Wv);
    qkv_mma<<<dim3(128, 3), 256, PROJ_SMEM>>>();
    attn_mma<<<dim3(4 * NQT, BATCH), 128, ATT_SMEM>>>();
    combine_kernel<<<(BATCH * SEQ * HD / 4) / 256, 256>>>(out);
}

// round 12
// speedup vs baseline: 3.1631x; 1.0683x over previous
#include <cuda_runtime.h>
#include <cuda_fp16.h>
#include <cstdint>

#define SEQ   4096
#define DM    1024
#define HD    128
#define BATCH 4
#define NQT   32          // SEQ / 128
// SCALE * log2(e): Q is pre-scaled so softmax is p = 2^s
#define QSCALE 0.1275174365f

__device__ __half g_xh[BATCH*SEQ*DM];
__device__ __half g_Wh[3*DM*HD];
__device__ __half g_Q[BATCH*SEQ*HD];
__device__ __half g_K[BATCH*SEQ*HD];
__device__ __half g_V[BATCH*SEQ*HD];
__device__ float  g_Op4[4][BATCH*SEQ*HD];
__device__ float  g_lp4[4][BATCH*SEQ];

// ---------------- helpers ----------------
__device__ __forceinline__ uint32_t smem_u32(const void* p) {
    uint32_t a;
    asm("{ .reg .u64 t; cvta.to.shared.u64 t, %1; cvt.u32.u64 %0, t; }" : "=r"(a) : "l"(p));
    return a;
}
__device__ __forceinline__ void ldsm4(uint32_t* r, uint32_t a) {
    asm volatile("ldmatrix.sync.aligned.m8n8.x4.shared.b16 {%0,%1,%2,%3}, [%4];"
        : "=r"(r[0]), "=r"(r[1]), "=r"(r[2]), "=r"(r[3]) : "r"(a));
}
__device__ __forceinline__ void ldsm4t(uint32_t* r, uint32_t a) {
    asm volatile("ldmatrix.sync.aligned.m8n8.x4.trans.shared.b16 {%0,%1,%2,%3}, [%4];"
        : "=r"(r[0]), "=r"(r[1]), "=r"(r[2]), "=r"(r[3]) : "r"(a));
}
__device__ __forceinline__ void mma16(float4& d, const uint32_t a[4], const uint32_t b[2]) {
    asm volatile(
        "mma.sync.aligned.m16n8k16.row.col.f32.f16.f16.f32 "
        "{%0,%1,%2,%3}, {%4,%5,%6,%7}, {%8,%9}, {%0,%1,%2,%3};"
        : "+f"(d.x), "+f"(d.y), "+f"(d.z), "+f"(d.w)
        : "r"(a[0]), "r"(a[1]), "r"(a[2]), "r"(a[3]), "r"(b[0]), "r"(b[1]));
}
__device__ __forceinline__ void cp16(uint32_t s, const void* g) {
    asm volatile("cp.async.cg.shared.global [%0], [%1], 16;" :: "r"(s), "l"(g));
}
#define CP_COMMIT() asm volatile("cp.async.commit_group;" ::: "memory")
template<int N> __device__ __forceinline__ void cp_wait() {
    asm volatile("cp.async.wait_group %0;" :: "n"(N) : "memory");
}
__device__ __forceinline__ uint32_t packh2(float a, float b) {
    __half2 h = __floats2half2_rn(a, b);
    return *(uint32_t*)&h;
}
__device__ __forceinline__ float ex2f(float x) {
    float y;
    asm("ex2.approx.f32 %0, %1;" : "=f"(y) : "f"(x));
    return y;
}

// ---------------------------------------------------------------------------
// Prepass: x (fp32) -> g_xh (fp16), Wq/Wk/Wv -> g_Wh
// ---------------------------------------------------------------------------
#define X_F4 (BATCH*SEQ*DM/4)      // 4194304
#define W_F4 (DM*HD/4)             // 32768
#define CVT_BLOCKS ((X_F4 + 3*W_F4) / 1024)   // 4192

__global__ __launch_bounds__(256)
void cvt_kernel(const float* __restrict__ x, const float* __restrict__ Wq,
                const float* __restrict__ Wk, const float* __restrict__ Wv)
{
    int i = blockIdx.x * 1024 + threadIdx.x;
    #pragma unroll
    for (int j = 0; j < 4; ++j, i += 256) {
        float4 v;
        __half* dst;
        if (i < X_F4) {
            v = ((const float4*)x)[i];
            dst = g_xh + (size_t)i * 4;
        } else {
            int wi = i - X_F4;
            int ws = wi >> 15, off = wi & 32767;
            const float* W = (ws == 0) ? Wq : (ws == 1) ? Wk : Wv;
            v = ((const float4*)W)[off];
            dst = g_Wh + (size_t)ws * (DM * HD) + (size_t)off * 4;
        }
        *(__half2*)dst       = __floats2half2_rn(v.x, v.y);
        *(__half2*)(dst + 2) = __floats2half2_rn(v.z, v.w);
    }
}

// ---------------------------------------------------------------------------
// QKV projection: C[16384,128] = xh @ Wh[wsel], fp16 mma + cp.async double buffer.
// Q output pre-scaled by QSCALE (softmax exp2 folding).
// ---------------------------------------------------------------------------
#define QA_H (128*40)
#define QB_H (32*136)
#define PROJ_SMEM ((2*QA_H + 2*QB_H) * 2)   // 37888 B

__global__ __launch_bounds__(256, 2)
void qkv_mma(void)
{
    extern __shared__ __half smh[];
    const uint32_t a_b = smem_u32(smh);
    const uint32_t b_b = a_b + 2 * QA_H * 2;

    const int tid  = threadIdx.x;
    const int lane = tid & 31, wid = tid >> 5;
    const int gr = lane >> 2, gc = lane & 3;
    const int wm = wid & 3, wn = wid >> 2;

    const int wsel = blockIdx.y;
    const __half* __restrict__ Wh = g_Wh + (size_t)wsel * (DM * HD);
    __half* __restrict__ C = (wsel == 0) ? g_Q : (wsel == 1) ? g_K : g_V;
    const float osc = (wsel == 0) ? QSCALE : 1.0f;
    const int m0 = blockIdx.x * 128;

    const int lrow  = ((lane >> 3) & 1) * 8 + (lane & 7);
    const int lcolA = (lane >> 4) * 8;

    float4 acc[2][8];
    #pragma unroll
    for (int i = 0; i < 2; i++)
        #pragma unroll
        for (int j = 0; j < 8; j++) acc[i][j] = make_float4(0.f, 0.f, 0.f, 0.f);

    auto issue = [&](int kc, int bsel) {
        uint32_t as = a_b + bsel * QA_H * 2;
        uint32_t bs = b_b + bsel * QB_H * 2;
        #pragma unroll
        for (int t = 0; t < 2; ++t) {
            int i = tid + t * 256;
            int r = i >> 2, u = i & 3;
            cp16(as + (uint32_t)((r * 40 + u * 8) * 2),
                 g_xh + ((size_t)(m0 + r)) * DM + kc * 32 + u * 8);
        }
        #pragma unroll
        for (int t = 0; t < 2; ++t) {
            int i = tid + t * 256;
            int r = i >> 4, u = i & 15;
            cp16(bs + (uint32_t)((r * 136 + u * 8) * 2),
                 Wh + (size_t)(kc * 32 + r) * HD + u * 8);
        }
    };

    int buf = 0;
    issue(0, 0); CP_COMMIT();
    for (int kc = 0; kc < 32; ++kc) {
        if (kc < 31) { issue(kc + 1, buf ^ 1); CP_COMMIT(); cp_wait<1>(); }
        else         { cp_wait<0>(); }
        __syncthreads();
        uint32_t as = a_b + buf * QA_H * 2;
        uint32_t bs = b_b + buf * QB_H * 2;
        #pragma unroll
        for (int ks = 0; ks < 2; ++ks) {
            const int k0 = ks * 16;
            uint32_t af[2][4];
            ldsm4(af[0], as + (uint32_t)(((wm * 32 + lrow) * 40 + k0 + lcolA) * 2));
            ldsm4(af[1], as + (uint32_t)(((wm * 32 + 16 + lrow) * 40 + k0 + lcolA) * 2));
            #pragma unroll
            for (int p = 0; p < 4; ++p) {
                int n0 = wn * 64 + p * 16;
                uint32_t bf[4];
                ldsm4t(bf, bs + (uint32_t)(((k0 + lrow) * 136 + n0 + lcolA) * 2));
                #pragma unroll
                for (int mf = 0; mf < 2; ++mf) {
                    mma16(acc[mf][2 * p],     af[mf], bf);
                    mma16(acc[mf][2 * p + 1], af[mf], bf + 2);
                }
            }
        }
        __syncthreads();
        buf ^= 1;
    }

    #pragma unroll
    for (int mf = 0; mf < 2; ++mf) {
        size_t r0 = (size_t)(m0 + wm * 32 + mf * 16 + gr);
        #pragma unroll
        for (int nf = 0; nf < 8; ++nf) {
            int col = wn * 64 + nf * 8 + 2 * gc;
            float4 v = acc[mf][nf];
            *(__half2*)&C[r0 * HD + col]       = __floats2half2_rn(v.x * osc, v.y * osc);
            *(__half2*)&C[(r0 + 8) * HD + col] = __floats2half2_rn(v.z * osc, v.w * osc);
        }
    }
}

// ---------------------------------------------------------------------------
// Flash attention: 128 threads, 4 warps x m32 slabs, P in registers,
// p = ex2(s) (Q pre-scaled), l via ones-MMA, masked-tile skip,
// cp.async double-buffered K/V, kv range split 4 ways per (b,qt).
// ---------------------------------------------------------------------------
#define SQ 136
#define NQ_H (128*SQ)
#define NK_H (64*SQ)
#define ATT_SMEM ((NQ_H + 4*NK_H) * 2)    // 104448 B
#define ONESH2 0x3C003C00u

__global__ __launch_bounds__(128, 2)
void attn_mma(void)
{
    extern __shared__ __half smh[];
    const uint32_t qs_b = smem_u32(smh);
    const uint32_t kv_b = qs_b + NQ_H * 2;

    const int tid  = threadIdx.x;
    const int lane = tid & 31, wid = tid >> 5;
    const int gr = lane >> 2, gc = lane & 3;
    const int wr = wid * 32;

    const int qt   = (NQT - 1) - (blockIdx.x >> 2);
    const int part = blockIdx.x & 3;
    const int b    = blockIdx.y;
    const int nkv  = 2 * qt + 2;
    const int kt0  = (nkv * part) >> 2;
    const int kt1  = (nkv * (part + 1)) >> 2;

    const int lrow  = ((lane >> 3) & 1) * 8 + (lane & 7);
    const int lcolA = (lane >> 4) * 8;
    const int brow  = (lane >> 4) * 8 + (lane & 7);
    const int bcol  = ((lane >> 3) & 1) * 8;

    auto issue_kv = [&](int kt, int bsel) {
        uint32_t ks = kv_b + (2 * bsel) * NK_H * 2;
        uint32_t vs = ks + NK_H * 2;
        const __half* Kg = g_K + ((size_t)b * SEQ + kt * 64) * HD;
        const __half* Vg = g_V + ((size_t)b * SEQ + kt * 64) * HD;
        #pragma unroll
        for (int t = 0; t < 8; ++t) {
            int i = tid + t * 128;
            int r = i >> 4, u = i & 15;
            uint32_t so = (uint32_t)((r * SQ + u * 8) * 2);
            cp16(ks + so, Kg + (size_t)r * HD + u * 8);
            cp16(vs + so, Vg + (size_t)r * HD + u * 8);
        }
    };

    {
        const __half* Qg = g_Q + ((size_t)b * SEQ + qt * 128) * HD;
        #pragma unroll
        for (int t = 0; t < 16; ++t) {
            int i = tid + t * 128;
            int r = i >> 4, u = i & 15;
            cp16(qs_b + (uint32_t)((r * SQ + u * 8) * 2), Qg + (size_t)r * HD + u * 8);
        }
        if (kt0 < kt1) issue_kv(kt0, 0);
        CP_COMMIT();
    }

    float4 oacc[2][16];
    float4 lacc[2];
    #pragma unroll
    for (int mf = 0; mf < 2; ++mf) {
        #pragma unroll
        for (int j = 0; j < 16; ++j) oacc[mf][j] = make_float4(0.f, 0.f, 0.f, 0.f);
        lacc[mf] = make_float4(0.f, 0.f, 0.f, 0.f);
    }

    const int rmin = qt * 128 + wr;       // warp's smallest q row
    const int qr0  = rmin + gr;
    const uint32_t ones[2] = { ONESH2, ONESH2 };

    int buf = 0;
    for (int kt = kt0; kt < kt1; ++kt) {
        if (kt + 1 < kt1) { issue_kv(kt + 1, buf ^ 1); CP_COMMIT(); cp_wait<1>(); }
        else              { cp_wait<0>(); }
        __syncthreads();

        if (kt * 64 <= rmin + 31) {       // else: warp fully masked for this tile
            const uint32_t kb = kv_b + (2 * buf) * NK_H * 2;
            const uint32_t vb_base = kb + NK_H * 2;

            uint32_t pf[2][8][2];
            #pragma unroll
            for (int h2 = 0; h2 < 2; ++h2) {
                float4 s[2][4];
                #pragma unroll
                for (int mf = 0; mf < 2; ++mf)
                    #pragma unroll
                    for (int j = 0; j < 4; ++j) s[mf][j] = make_float4(0.f, 0.f, 0.f, 0.f);
                #pragma unroll
                for (int ks = 0; ks < 8; ++ks) {
                    const int k0 = ks * 16;
                    uint32_t af[2][4];
                    ldsm4(af[0], qs_b + (uint32_t)(((wr + lrow) * SQ + k0 + lcolA) * 2));
                    ldsm4(af[1], qs_b + (uint32_t)(((wr + 16 + lrow) * SQ + k0 + lcolA) * 2));
                    #pragma unroll
                    for (int p = 0; p < 2; ++p) {
                        int n0 = h2 * 32 + p * 16;
                        uint32_t bf[4];
                        ldsm4(bf, kb + (uint32_t)(((n0 + brow) * SQ + k0 + bcol) * 2));
                        #pragma unroll
                        for (int mf = 0; mf < 2; ++mf) {
                            mma16(s[mf][2 * p],     af[mf], bf);
                            mma16(s[mf][2 * p + 1], af[mf], bf + 2);
                        }
                    }
                }
                const int kvb = kt * 64 + h2 * 32;
                if (kvb + 31 > rmin) {
                    // diagonal: mask then exp2
                    #pragma unroll
                    for (int mf = 0; mf < 2; ++mf) {
                        const int r0 = qr0 + mf * 16, r1 = r0 + 8;
                        #pragma unroll
                        for (int nf = 0; nf < 4; ++nf) {
                            int c = kvb + nf * 8 + 2 * gc;
                            float4 sv = s[mf][nf];
                            float e0 = (c     <= r0) ? ex2f(sv.x) : 0.f;
                            float e1 = (c + 1 <= r0) ? ex2f(sv.y) : 0.f;
                            float e2 = (c     <= r1) ? ex2f(sv.z) : 0.f;
                            float e3 = (c + 1 <= r1) ? ex2f(sv.w) : 0.f;
                            pf[mf][h2 * 4 + nf][0] = packh2(e0, e1);
                            pf[mf][h2 * 4 + nf][1] = packh2(e2, e3);
                        }
                    }
                } else {
                    // interior: straight exp2
                    #pragma unroll
                    for (int mf = 0; mf < 2; ++mf)
                        #pragma unroll
                        for (int nf = 0; nf < 4; ++nf) {
                            float4 sv = s[mf][nf];
                            pf[mf][h2 * 4 + nf][0] = packh2(ex2f(sv.x), ex2f(sv.y));
                            pf[mf][h2 * 4 + nf][1] = packh2(ex2f(sv.z), ex2f(sv.w));
                        }
                }
            }

            // ---- O += P V ; l += P 1 ----
            #pragma unroll
            for (int ks = 0; ks < 4; ++ks) {
                uint32_t pa[2][4];
                #pragma unroll
                for (int mf = 0; mf < 2; ++mf) {
                    pa[mf][0] = pf[mf][2 * ks][0];     pa[mf][1] = pf[mf][2 * ks][1];
                    pa[mf][2] = pf[mf][2 * ks + 1][0]; pa[mf][3] = pf[mf][2 * ks + 1][1];
                    mma16(lacc[mf], pa[mf], ones);
                }
                #pragma unroll
                for (int p = 0; p < 8; ++p) {
                    int n0 = p * 16;
                    uint32_t vb[4];
                    ldsm4t(vb, vb_base + (uint32_t)(((ks * 16 + lrow) * SQ + n0 + lcolA) * 2));
                    #pragma unroll
                    for (int mf = 0; mf < 2; ++mf) {
                        mma16(oacc[mf][2 * p],     pa[mf], vb);
                        mma16(oacc[mf][2 * p + 1], pa[mf], vb + 2);
                    }
                }
            }
        }
        __syncthreads();
        buf ^= 1;
    }
    cp_wait<0>();

    // ---- write unnormalized partials (l rows from lacc: .x row gr, .z row gr+8) ----
    float* Op = g_Op4[part];
    float* lp = g_lp4[part];
    #pragma unroll
    for (int mf = 0; mf < 2; ++mf) {
        const size_t r0 = (size_t)b * SEQ + qt * 128 + wr + mf * 16 + gr;
        #pragma unroll
        for (int nf = 0; nf < 16; ++nf) {
            int col = nf * 8 + 2 * gc;
            float4 v = oacc[mf][nf];
            *(float2*)&Op[r0 * HD + col]       = make_float2(v.x, v.y);
            *(float2*)&Op[(r0 + 8) * HD + col] = make_float2(v.z, v.w);
        }
        if (gc == 0) {
            lp[r0]     = lacc[mf].x;
            lp[r0 + 8] = lacc[mf].z;
        }
    }
}

// ---------------------------------------------------------------------------
__global__ __launch_bounds__(256)
void combine_kernel(float* __restrict__ out)
{
    int idx = blockIdx.x * 256 + threadIdx.x;
    int row = idx >> 5;
    float inv = 1.f / (g_lp4[0][row] + g_lp4[1][row] + g_lp4[2][row] + g_lp4[3][row]);
    float4 a = ((const float4*)g_Op4[0])[idx];
    float4 c = ((const float4*)g_Op4[1])[idx];
    float4 d = ((const float4*)g_Op4[2])[idx];
    float4 e = ((const float4*)g_Op4[3])[idx];
    ((float4*)out)[idx] = make_float4((a.x + c.x + d.x + e.x) * inv,
                                      (a.y + c.y + d.y + e.y) * inv,
                                      (a.z + c.z + d.z + e.z) * inv,
                                      (a.w + c.w + d.w + e.w) * inv);
}

// ---------------------------------------------------------------------------
extern "C" void kernel_launch(void* const* d_in, const int* in_sizes, int n_in,
                              void* d_out, int out_size)
{
    const float* x  = (const float*)d_in[0];
    const float* Wq = (const float*)d_in[1];
    const float* Wk = (const float*)d_in[2];
    const float* Wv = (const float*)d_in[3];
    float* out = (float*)d_out;

    cudaFuncSetAttribute(qkv_mma, cudaFuncAttributeMaxDynamicSharedMemorySize, PROJ_SMEM);
    cudaFuncSetAttribute(attn_mma, cudaFuncAttributeMaxDynamicSharedMemorySize, ATT_SMEM);

    cvt_kernel<<<CVT_BLOCKS, 256>>>(x, Wq, Wk, Wv);
    qkv_mma<<<dim3(128, 3), 256, PROJ_SMEM>>>();
    attn_mma<<<dim3(4 * NQT, BATCH), 128, ATT_SMEM>>>();
    combine_kernel<<<(BATCH * SEQ * HD / 4) / 256, 256>>>(out);
}

// round 13
// speedup vs baseline: 3.2560x; 1.0294x over previous
#include <cuda_runtime.h>
#include <cuda_fp16.h>
#include <cstdint>

#define SEQ   4096
#define DM    1024
#define HD    128
#define BATCH 4
#define NQT   32          // SEQ / 128
// SCALE * log2(e): Q is pre-scaled so softmax is p = 2^s
#define QSCALE 0.1275174365f

__device__ __half g_xh[BATCH*SEQ*DM];
__device__ __half g_Wh[3*DM*HD];
__device__ __half g_Q[BATCH*SEQ*HD];
__device__ __half g_K[BATCH*SEQ*HD];
__device__ __half g_V[BATCH*SEQ*HD];
__device__ float  g_Op4[4][BATCH*SEQ*HD];
__device__ float  g_lp4[4][BATCH*SEQ];

// ---------------- helpers ----------------
__device__ __forceinline__ uint32_t smem_u32(const void* p) {
    uint32_t a;
    asm("{ .reg .u64 t; cvta.to.shared.u64 t, %1; cvt.u32.u64 %0, t; }" : "=r"(a) : "l"(p));
    return a;
}
__device__ __forceinline__ void ldsm4(uint32_t* r, uint32_t a) {
    asm volatile("ldmatrix.sync.aligned.m8n8.x4.shared.b16 {%0,%1,%2,%3}, [%4];"
        : "=r"(r[0]), "=r"(r[1]), "=r"(r[2]), "=r"(r[3]) : "r"(a));
}
__device__ __forceinline__ void ldsm4t(uint32_t* r, uint32_t a) {
    asm volatile("ldmatrix.sync.aligned.m8n8.x4.trans.shared.b16 {%0,%1,%2,%3}, [%4];"
        : "=r"(r[0]), "=r"(r[1]), "=r"(r[2]), "=r"(r[3]) : "r"(a));
}
__device__ __forceinline__ void mma16(float4& d, const uint32_t a[4], const uint32_t b[2]) {
    asm volatile(
        "mma.sync.aligned.m16n8k16.row.col.f32.f16.f16.f32 "
        "{%0,%1,%2,%3}, {%4,%5,%6,%7}, {%8,%9}, {%0,%1,%2,%3};"
        : "+f"(d.x), "+f"(d.y), "+f"(d.z), "+f"(d.w)
        : "r"(a[0]), "r"(a[1]), "r"(a[2]), "r"(a[3]), "r"(b[0]), "r"(b[1]));
}
__device__ __forceinline__ void cp16(uint32_t s, const void* g) {
    asm volatile("cp.async.cg.shared.global [%0], [%1], 16;" :: "r"(s), "l"(g));
}
#define CP_COMMIT() asm volatile("cp.async.commit_group;" ::: "memory")
template<int N> __device__ __forceinline__ void cp_wait() {
    asm volatile("cp.async.wait_group %0;" :: "n"(N) : "memory");
}
__device__ __forceinline__ uint32_t packh2(float a, float b) {
    __half2 h = __floats2half2_rn(a, b);
    return *(uint32_t*)&h;
}
__device__ __forceinline__ float ex2f(float x) {
    float y;
    asm("ex2.approx.f32 %0, %1;" : "=f"(y) : "f"(x));
    return y;
}
__device__ __forceinline__ uint32_t ex2h2(uint32_t x) {
    uint32_t y;
    asm("ex2.approx.f16x2 %0, %1;" : "=r"(y) : "r"(x));
    return y;
}

// ---------------------------------------------------------------------------
// Prepass: x (fp32) -> g_xh (fp16), Wq/Wk/Wv -> g_Wh
// ---------------------------------------------------------------------------
#define X_F4 (BATCH*SEQ*DM/4)      // 4194304
#define W_F4 (DM*HD/4)             // 32768
#define CVT_BLOCKS ((X_F4 + 3*W_F4) / 1024)   // 4192

__global__ __launch_bounds__(256)
void cvt_kernel(const float* __restrict__ x, const float* __restrict__ Wq,
                const float* __restrict__ Wk, const float* __restrict__ Wv)
{
    int i = blockIdx.x * 1024 + threadIdx.x;
    #pragma unroll
    for (int j = 0; j < 4; ++j, i += 256) {
        float4 v;
        __half* dst;
        if (i < X_F4) {
            v = ((const float4*)x)[i];
            dst = g_xh + (size_t)i * 4;
        } else {
            int wi = i - X_F4;
            int ws = wi >> 15, off = wi & 32767;
            const float* W = (ws == 0) ? Wq : (ws == 1) ? Wk : Wv;
            v = ((const float4*)W)[off];
            dst = g_Wh + (size_t)ws * (DM * HD) + (size_t)off * 4;
        }
        *(__half2*)dst       = __floats2half2_rn(v.x, v.y);
        *(__half2*)(dst + 2) = __floats2half2_rn(v.z, v.w);
    }
}

// ---------------------------------------------------------------------------
// QKV projection: C[16384,128] = xh @ Wh[wsel], fp16 mma + cp.async double buffer.
// Q output pre-scaled by QSCALE (softmax exp2 folding).
// ---------------------------------------------------------------------------
#define QA_H (128*40)
#define QB_H (32*136)
#define PROJ_SMEM ((2*QA_H + 2*QB_H) * 2)   // 37888 B

__global__ __launch_bounds__(256, 2)
void qkv_mma(void)
{
    extern __shared__ __half smh[];
    const uint32_t a_b = smem_u32(smh);
    const uint32_t b_b = a_b + 2 * QA_H * 2;

    const int tid  = threadIdx.x;
    const int lane = tid & 31, wid = tid >> 5;
    const int gr = lane >> 2, gc = lane & 3;
    const int wm = wid & 3, wn = wid >> 2;

    const int wsel = blockIdx.y;
    const __half* __restrict__ Wh = g_Wh + (size_t)wsel * (DM * HD);
    __half* __restrict__ C = (wsel == 0) ? g_Q : (wsel == 1) ? g_K : g_V;
    const float osc = (wsel == 0) ? QSCALE : 1.0f;
    const int m0 = blockIdx.x * 128;

    const int lrow  = ((lane >> 3) & 1) * 8 + (lane & 7);
    const int lcolA = (lane >> 4) * 8;

    float4 acc[2][8];
    #pragma unroll
    for (int i = 0; i < 2; i++)
        #pragma unroll
        for (int j = 0; j < 8; j++) acc[i][j] = make_float4(0.f, 0.f, 0.f, 0.f);

    auto issue = [&](int kc, int bsel) {
        uint32_t as = a_b + bsel * QA_H * 2;
        uint32_t bs = b_b + bsel * QB_H * 2;
        #pragma unroll
        for (int t = 0; t < 2; ++t) {
            int i = tid + t * 256;
            int r = i >> 2, u = i & 3;
            cp16(as + (uint32_t)((r * 40 + u * 8) * 2),
                 g_xh + ((size_t)(m0 + r)) * DM + kc * 32 + u * 8);
        }
        #pragma unroll
        for (int t = 0; t < 2; ++t) {
            int i = tid + t * 256;
            int r = i >> 4, u = i & 15;
            cp16(bs + (uint32_t)((r * 136 + u * 8) * 2),
                 Wh + (size_t)(kc * 32 + r) * HD + u * 8);
        }
    };

    int buf = 0;
    issue(0, 0); CP_COMMIT();
    for (int kc = 0; kc < 32; ++kc) {
        if (kc < 31) { issue(kc + 1, buf ^ 1); CP_COMMIT(); cp_wait<1>(); }
        else         { cp_wait<0>(); }
        __syncthreads();
        uint32_t as = a_b + buf * QA_H * 2;
        uint32_t bs = b_b + buf * QB_H * 2;
        #pragma unroll
        for (int ks = 0; ks < 2; ++ks) {
            const int k0 = ks * 16;
            uint32_t af[2][4];
            ldsm4(af[0], as + (uint32_t)(((wm * 32 + lrow) * 40 + k0 + lcolA) * 2));
            ldsm4(af[1], as + (uint32_t)(((wm * 32 + 16 + lrow) * 40 + k0 + lcolA) * 2));
            #pragma unroll
            for (int p = 0; p < 4; ++p) {
                int n0 = wn * 64 + p * 16;
                uint32_t bf[4];
                ldsm4t(bf, bs + (uint32_t)(((k0 + lrow) * 136 + n0 + lcolA) * 2));
                #pragma unroll
                for (int mf = 0; mf < 2; ++mf) {
                    mma16(acc[mf][2 * p],     af[mf], bf);
                    mma16(acc[mf][2 * p + 1], af[mf], bf + 2);
                }
            }
        }
        __syncthreads();
        buf ^= 1;
    }

    #pragma unroll
    for (int mf = 0; mf < 2; ++mf) {
        size_t r0 = (size_t)(m0 + wm * 32 + mf * 16 + gr);
        #pragma unroll
        for (int nf = 0; nf < 8; ++nf) {
            int col = wn * 64 + nf * 8 + 2 * gc;
            float4 v = acc[mf][nf];
            *(__half2*)&C[r0 * HD + col]       = __floats2half2_rn(v.x * osc, v.y * osc);
            *(__half2*)&C[(r0 + 8) * HD + col] = __floats2half2_rn(v.z * osc, v.w * osc);
        }
    }
}

// ---------------------------------------------------------------------------
// Flash attention: 128 threads, 4 warps x m32 slabs, P in registers,
// p = ex2 (Q pre-scaled; f16x2 MUFU on interior tiles), l via ones-MMA,
// masked-tile skip, cp.async double-buffered K/V, 4-way kv split.
// ---------------------------------------------------------------------------
#define SQ 136
#define NQ_H (128*SQ)
#define NK_H (64*SQ)
#define ATT_SMEM ((NQ_H + 4*NK_H) * 2)    // 104448 B
#define ONESH2 0x3C003C00u

__global__ __launch_bounds__(128, 2)
void attn_mma(void)
{
    extern __shared__ __half smh[];
    const uint32_t qs_b = smem_u32(smh);
    const uint32_t kv_b = qs_b + NQ_H * 2;

    const int tid  = threadIdx.x;
    const int lane = tid & 31, wid = tid >> 5;
    const int gr = lane >> 2, gc = lane & 3;
    const int wr = wid * 32;

    const int qt   = (NQT - 1) - (blockIdx.x >> 2);
    const int part = blockIdx.x & 3;
    const int b    = blockIdx.y;
    const int nkv  = 2 * qt + 2;
    const int kt0  = (nkv * part) >> 2;
    const int kt1  = (nkv * (part + 1)) >> 2;

    const int lrow  = ((lane >> 3) & 1) * 8 + (lane & 7);
    const int lcolA = (lane >> 4) * 8;
    const int brow  = (lane >> 4) * 8 + (lane & 7);
    const int bcol  = ((lane >> 3) & 1) * 8;

    auto issue_kv = [&](int kt, int bsel) {
        uint32_t ks = kv_b + (2 * bsel) * NK_H * 2;
        uint32_t vs = ks + NK_H * 2;
        const __half* Kg = g_K + ((size_t)b * SEQ + kt * 64) * HD;
        const __half* Vg = g_V + ((size_t)b * SEQ + kt * 64) * HD;
        #pragma unroll
        for (int t = 0; t < 8; ++t) {
            int i = tid + t * 128;
            int r = i >> 4, u = i & 15;
            uint32_t so = (uint32_t)((r * SQ + u * 8) * 2);
            cp16(ks + so, Kg + (size_t)r * HD + u * 8);
            cp16(vs + so, Vg + (size_t)r * HD + u * 8);
        }
    };

    {
        const __half* Qg = g_Q + ((size_t)b * SEQ + qt * 128) * HD;
        #pragma unroll
        for (int t = 0; t < 16; ++t) {
            int i = tid + t * 128;
            int r = i >> 4, u = i & 15;
            cp16(qs_b + (uint32_t)((r * SQ + u * 8) * 2), Qg + (size_t)r * HD + u * 8);
        }
        if (kt0 < kt1) issue_kv(kt0, 0);
        CP_COMMIT();
    }

    float4 oacc[2][16];
    float4 lacc[2];
    #pragma unroll
    for (int mf = 0; mf < 2; ++mf) {
        #pragma unroll
        for (int j = 0; j < 16; ++j) oacc[mf][j] = make_float4(0.f, 0.f, 0.f, 0.f);
        lacc[mf] = make_float4(0.f, 0.f, 0.f, 0.f);
    }

    const int rmin = qt * 128 + wr;       // warp's smallest q row
    const int qr0  = rmin + gr;
    const uint32_t ones[2] = { ONESH2, ONESH2 };

    int buf = 0;
    for (int kt = kt0; kt < kt1; ++kt) {
        if (kt + 1 < kt1) { issue_kv(kt + 1, buf ^ 1); CP_COMMIT(); cp_wait<1>(); }
        else              { cp_wait<0>(); }
        __syncthreads();

        if (kt * 64 <= rmin + 31) {       // else: warp fully masked for this tile
            const uint32_t kb = kv_b + (2 * buf) * NK_H * 2;
            const uint32_t vb_base = kb + NK_H * 2;

            // ---- S = Q K^T : m32 x n64, ks-outer (Q frags loaded once) ----
            float4 s[2][8];
            #pragma unroll
            for (int mf = 0; mf < 2; ++mf)
                #pragma unroll
                for (int j = 0; j < 8; ++j) s[mf][j] = make_float4(0.f, 0.f, 0.f, 0.f);
            #pragma unroll
            for (int ks = 0; ks < 8; ++ks) {
                const int k0 = ks * 16;
                uint32_t af[2][4];
                ldsm4(af[0], qs_b + (uint32_t)(((wr + lrow) * SQ + k0 + lcolA) * 2));
                ldsm4(af[1], qs_b + (uint32_t)(((wr + 16 + lrow) * SQ + k0 + lcolA) * 2));
                #pragma unroll
                for (int p = 0; p < 4; ++p) {
                    uint32_t bf[4];
                    ldsm4(bf, kb + (uint32_t)(((p * 16 + brow) * SQ + k0 + bcol) * 2));
                    #pragma unroll
                    for (int mf = 0; mf < 2; ++mf) {
                        mma16(s[mf][2 * p],     af[mf], bf);
                        mma16(s[mf][2 * p + 1], af[mf], bf + 2);
                    }
                }
            }

            // ---- softmax: p = 2^s ----
            uint32_t pf[2][8][2];
            if (kt * 64 + 63 > rmin) {
                // diagonal tile: scalar mask + ex2.f32
                #pragma unroll
                for (int mf = 0; mf < 2; ++mf) {
                    const int r0 = qr0 + mf * 16, r1 = r0 + 8;
                    #pragma unroll
                    for (int nf = 0; nf < 8; ++nf) {
                        int c = kt * 64 + nf * 8 + 2 * gc;
                        float4 sv = s[mf][nf];
                        float e0 = (c     <= r0) ? ex2f(sv.x) : 0.f;
                        float e1 = (c + 1 <= r0) ? ex2f(sv.y) : 0.f;
                        float e2 = (c     <= r1) ? ex2f(sv.z) : 0.f;
                        float e3 = (c + 1 <= r1) ? ex2f(sv.w) : 0.f;
                        pf[mf][nf][0] = packh2(e0, e1);
                        pf[mf][nf][1] = packh2(e2, e3);
                    }
                }
            } else {
                // interior: pack to f16x2 first, one MUFU per pair
                #pragma unroll
                for (int mf = 0; mf < 2; ++mf)
                    #pragma unroll
                    for (int nf = 0; nf < 8; ++nf) {
                        float4 sv = s[mf][nf];
                        pf[mf][nf][0] = ex2h2(packh2(sv.x, sv.y));
                        pf[mf][nf][1] = ex2h2(packh2(sv.z, sv.w));
                    }
            }

            // ---- O += P V ; l += P 1 ----
            #pragma unroll
            for (int ks = 0; ks < 4; ++ks) {
                uint32_t pa[2][4];
                #pragma unroll
                for (int mf = 0; mf < 2; ++mf) {
                    pa[mf][0] = pf[mf][2 * ks][0];     pa[mf][1] = pf[mf][2 * ks][1];
                    pa[mf][2] = pf[mf][2 * ks + 1][0]; pa[mf][3] = pf[mf][2 * ks + 1][1];
                    mma16(lacc[mf], pa[mf], ones);
                }
                #pragma unroll
                for (int p = 0; p < 8; ++p) {
                    int n0 = p * 16;
                    uint32_t vb[4];
                    ldsm4t(vb, vb_base + (uint32_t)(((ks * 16 + lrow) * SQ + n0 + lcolA) * 2));
                    #pragma unroll
                    for (int mf = 0; mf < 2; ++mf) {
                        mma16(oacc[mf][2 * p],     pa[mf], vb);
                        mma16(oacc[mf][2 * p + 1], pa[mf], vb + 2);
                    }
                }
            }
        }
        __syncthreads();
        buf ^= 1;
    }
    cp_wait<0>();

    // ---- write unnormalized partials (l rows from lacc: .x row gr, .z row gr+8) ----
    float* Op = g_Op4[part];
    float* lp = g_lp4[part];
    #pragma unroll
    for (int mf = 0; mf < 2; ++mf) {
        const size_t r0 = (size_t)b * SEQ + qt * 128 + wr + mf * 16 + gr;
        #pragma unroll
        for (int nf = 0; nf < 16; ++nf) {
            int col = nf * 8 + 2 * gc;
            float4 v = oacc[mf][nf];
            *(float2*)&Op[r0 * HD + col]       = make_float2(v.x, v.y);
            *(float2*)&Op[(r0 + 8) * HD + col] = make_float2(v.z, v.w);
        }
        if (gc == 0) {
            lp[r0]     = lacc[mf].x;
            lp[r0 + 8] = lacc[mf].z;
        }
    }
}

// ---------------------------------------------------------------------------
__global__ __launch_bounds__(256)
void combine_kernel(float* __restrict__ out)
{
    int idx0 = blockIdx.x * 512 + threadIdx.x;   // over 16384*32 float4, 2 per thread
    #pragma unroll
    for (int j = 0; j < 2; ++j) {
        int idx = idx0 + j * 256;
        int row = idx >> 5;
        float l0 = g_lp4[0][row], l1 = g_lp4[1][row];
        float l2 = g_lp4[2][row], l3 = g_lp4[3][row];
        float4 a = ((const float4*)g_Op4[0])[idx];
        float4 c = ((const float4*)g_Op4[1])[idx];
        float4 d = ((const float4*)g_Op4[2])[idx];
        float4 e = ((const float4*)g_Op4[3])[idx];
        float inv = 1.f / (l0 + l1 + l2 + l3);
        ((float4*)out)[idx] = make_float4((a.x + c.x + d.x + e.x) * inv,
                                          (a.y + c.y + d.y + e.y) * inv,
                                          (a.z + c.z + d.z + e.z) * inv,
                                          (a.w + c.w + d.w + e.w) * inv);
    }
}

// ---------------------------------------------------------------------------
extern "C" void kernel_launch(void* const* d_in, const int* in_sizes, int n_in,
                              void* d_out, int out_size)
{
    const float* x  = (const float*)d_in[0];
    const float* Wq = (const float*)d_in[1];
    const float* Wk = (const float*)d_in[2];
    const float* Wv = (const float*)d_in[3];
    float* out = (float*)d_out;

    cudaFuncSetAttribute(qkv_mma, cudaFuncAttributeMaxDynamicSharedMemorySize, PROJ_SMEM);
    cudaFuncSetAttribute(attn_mma, cudaFuncAttributeMaxDynamicSharedMemorySize, ATT_SMEM);

    cvt_kernel<<<CVT_BLOCKS, 256>>>(x, Wq, Wk, Wv);
    qkv_mma<<<dim3(128, 3), 256, PROJ_SMEM>>>();
    attn_mma<<<dim3(4 * NQT, BATCH), 128, ATT_SMEM>>>();
    combine_kernel<<<(BATCH * SEQ * HD / 4) / 512, 256>>>(out);
}